// round 11
// baseline (speedup 1.0000x reference)
#include <cuda_runtime.h>
#include <math.h>
#include <stdint.h>

// ---------------------------------------------------------------------------
// SimpleVQ: B=32, H=1, L=4096, D=64, S=512
// out (f32): quantized[NVEC*64] | z[NVEC] | l_commit | errs2[NVEC]
// Chebyshev-compressed scan (17 FFMA2/code) on the 256-thread R1 chassis,
// register-resident top-3 margin certification, exact fp32 refine.
// ---------------------------------------------------------------------------

typedef unsigned long long ull;

#define NVEC   131072
#define NCODE  512
#define ZOFF   8388608
#define LOFF   8519680
#define EOFF   8519681
#define NBLK   148
#define NTHR   256
#define NTILES 512             // NVEC / NTHR

#define JHEAD  12
#define NSEQ   40
#define TROW   18              // table row: 12 head ull + 5 poly ull + (cn,pad)

// ---- smem layout (bytes) ---------------------------------------------------
#define SCB    0               // fp32 codebook [512][64]      131072
#define STBL   131072          // packed table [512][18] ull    73728
#define SCF    204800          // coef [40][9] f32               1440
#define SGE    206240          // E [40] f32                      160
#define SRED   206400          // float[256]                     1024
#define SMEM_BYTES 207424

__device__ float g_cbf[512 * 64];
__device__ float g_cn[512];
__device__ float g_rt[512];
__device__ ull   g_TBL[512 * TROW];
__device__ float g_cf[NSEQ * 9];
__device__ float g_E[NSEQ];
__device__ float g_part[NBLK];

// ---- packed f32x2 helpers (verified in R1) ---------------------------------
__device__ __forceinline__ ull pack2(float lo, float hi) {
    ull r; asm("mov.b64 %0, {%1, %2};" : "=l"(r) : "f"(lo), "f"(hi)); return r;
}
__device__ __forceinline__ void unpack2(ull v, float &lo, float &hi) {
    asm("mov.b64 {%0, %1}, %2;" : "=f"(lo), "=f"(hi) : "l"(v));
}
__device__ __forceinline__ void ffma2(ull &acc, ull a, ull b) {
    asm("fma.rn.f32x2 %0, %1, %2, %0;" : "+l"(acc) : "l"(a), "l"(b));
}

// ---------------------------------------------------------------------------
// Init 1: codebook (double trig; identical to all passing rounds)
// ---------------------------------------------------------------------------
__global__ void vq_init() {
    __shared__ float red[64];
    const int s = blockIdx.x;
    const int d = threadIdx.x;
    const int j = d & 31;

    double expn = -((double)(2 * j) / 64.0);
    float  il   = (float)pow(100000.0, expn);
    float  pre  = __fmul_rn((float)s, il);
    float  e    = (d < 32) ? (float)sin((double)pre) : (float)cos((double)pre);

    red[d] = __fmul_rn(e, e);
    __syncthreads();
    for (int o = 32; o > 0; o >>= 1) {
        if (d < o) red[d] = __fadd_rn(red[d], red[d + o]);
        __syncthreads();
    }
    float m = __fadd_rn(__fmul_rn(red[0], (1.0f / 64.0f)), 1e-6f);
    __syncthreads();
    float r = (float)(1.0 / sqrt((double)m));
    float c = __fmul_rn(__fmul_rn(e, r), 0.35355339059327373f);

    g_cbf[s * 64 + d] = c;
    if (d == 0) g_rt[s] = __fmul_rn(r, 0.35355339059327373f);

    red[d] = __fmul_rn(c, c);
    __syncthreads();
    for (int o = 32; o > 0; o >>= 1) {
        if (d < o) red[d] = __fadd_rn(red[d], red[d + o]);
        __syncthreads();
    }
    if (d == 0) g_cn[s] = red[0];
}

// ---------------------------------------------------------------------------
// Init 2: Chebyshev fits + certified errors (unchanged, passed twice)
//         + packed table build.
// ---------------------------------------------------------------------------
__global__ void vq_init2() {
    __shared__ float scf[NSEQ][9];
    __shared__ int   seps[NSEQ];
    __shared__ float red[512];
    const int t = threadIdx.x;

    if (t < NSEQ) {
        const int jj = t >> 1, trig = t & 1;
        const int j  = JHEAD + jj;
        float w = (float)pow(100000.0, -((double)(2 * j) / 64.0));
        float c[9];
#pragma unroll
        for (int k = 0; k < 9; k++) c[k] = 0.f;
        for (int mnode = 0; mnode < 33; mnode++) {
            float th = (float)M_PI * ((float)mnode + 0.5f) / 33.f;
            float ct = cosf(th);
            float x  = 255.5f + 255.5f * ct;
            float f  = trig ? cosf(w * x) : sinf(w * x);
            float tk0 = 1.f, tk1 = ct;
            c[0] += f; c[1] += f * ct;
#pragma unroll
            for (int k = 2; k < 9; k++) {
                float tk = 2.f * ct * tk1 - tk0;
                c[k] += f * tk;
                tk0 = tk1; tk1 = tk;
            }
        }
#pragma unroll
        for (int k = 0; k < 9; k++) c[k] *= (2.f / 33.f);
        c[0] *= 0.5f;
#pragma unroll
        for (int k = 0; k < 9; k++) { scf[t][k] = c[k]; g_cf[t * 9 + k] = c[k]; }
        seps[t] = 0;
    }
    __syncthreads();

    const int s = t;
    const float rt = g_rt[s];
    double y = ((double)s - 255.5) / 255.5;
    double T[9];
    T[0] = 1.0; T[1] = y;
#pragma unroll
    for (int k = 2; k < 9; k++) T[k] = 2.0 * y * T[k - 1] - T[k - 2];

    // packed table row
    {
        ull* row = g_TBL + s * TROW;
        float pt[9];
#pragma unroll
        for (int k = 0; k < 9; k++) pt[k] = (float)((double)rt * T[k]);
#pragma unroll
        for (int j = 0; j < JHEAD; j++) {
            float lo = g_cbf[s * 64 + j];
            float hi = g_cbf[s * 64 + 32 + j];
            row[j] = ((ull)__float_as_uint(hi) << 32) | __float_as_uint(lo);
        }
#pragma unroll
        for (int k = 0; k < 4; k++)
            row[12 + k] = ((ull)__float_as_uint(pt[2 * k + 1]) << 32)
                        | __float_as_uint(pt[2 * k]);
        row[16] = (ull)__float_as_uint(pt[8]);   // (pt8, 0)
        row[17] = (ull)__float_as_uint(g_cn[s]); // (cn, 0)
    }

    // certified eps (truth = exact kernel-1 formula)
    for (int q = 0; q < NSEQ; q++) {
        const int jj = q >> 1, trig = q & 1;
        const int j  = JHEAD + jj;
        double expn = -((double)(2 * j) / 64.0);
        float  il   = (float)pow(100000.0, expn);
        float  pre  = __fmul_rn((float)s, il);
        double truth = trig ? cos((double)pre) : sin((double)pre);
        double fit = 0.0;
#pragma unroll
        for (int k = 0; k < 9; k++) fit += (double)scf[q][k] * T[k];
        float err = (float)fabs(truth - fit);
        atomicMax(&seps[q], __float_as_int(err));
    }

    red[t] = rt;
    __syncthreads();
    for (int o = 256; o > 0; o >>= 1) {
        if (t < o) red[t] = fmaxf(red[t], red[t + o]);
        __syncthreads();
    }
    if (t < NSEQ) g_E[t] = __int_as_float(seps[t]) * red[0];
}

// ---------------------------------------------------------------------------
__global__ void __launch_bounds__(NTHR) vq_main(const float* __restrict__ vecs,
                                                const float* __restrict__ mask,
                                                float* __restrict__ out) {
    extern __shared__ unsigned char smem[];
    float* scb  = (float*)(smem + SCB);
    ull*   stbl = (ull*)(smem + STBL);
    float* scf  = (float*)(smem + SCF);
    float* sge  = (float*)(smem + SGE);
    float* sred = (float*)(smem + SRED);

    const int t = threadIdx.x;

    // ---- stage codebook + table + coefs into smem ----
    {
        uint4* d4 = (uint4*)scb;
        const uint4* s4 = (const uint4*)g_cbf;
        for (int i = t; i < (512 * 64 * 4) / 16; i += NTHR) d4[i] = s4[i];
        uint4* t4 = (uint4*)stbl;
        const uint4* u4 = (const uint4*)g_TBL;
        for (int i = t; i < (512 * TROW * 8) / 16; i += NTHR) t4[i] = u4[i];
        for (int i = t; i < NSEQ * 9; i += NTHR) scf[i] = g_cf[i];
        if (t < NSEQ) sge[t] = g_E[t];
    }
    __syncthreads();

    float lacc = 0.f;

    for (int tile = blockIdx.x; tile < NTILES; tile += NBLK) {
        const int vglob = tile * NTHR + t;
        const float* vrow = vecs + (size_t)vglob * 64;

        // ---- stream row: exact ascending vn, head capture, beta build ----
        float hlo[JHEAD], hhi[JHEAD];
        float beta[9];
#pragma unroll
        for (int k = 0; k < 9; k++) beta[k] = 0.f;
        float errb = 0.f;
        float vn = 0.f;
        {
            const float4* vp = (const float4*)vrow;
#pragma unroll
            for (int i = 0; i < 16; i++) {
                float4 x = vp[i];
                vn = __fadd_rn(vn, __fmul_rn(x.x, x.x));
                vn = __fadd_rn(vn, __fmul_rn(x.y, x.y));
                vn = __fadd_rn(vn, __fmul_rn(x.z, x.z));
                vn = __fadd_rn(vn, __fmul_rn(x.w, x.w));
                float c4[4] = {x.x, x.y, x.z, x.w};
#pragma unroll
                for (int cc = 0; cc < 4; cc++) {
                    const int d = 4 * i + cc;
                    if (d < 12)            hlo[d] = c4[cc];
                    else if (d < 32) {     // tail sin: q = 2*(d-12)
                        const int q = 2 * (d - 12);
                        const float v = c4[cc];
                        const float* cf = scf + q * 9;
#pragma unroll
                        for (int k = 0; k < 9; k++) beta[k] = fmaf(v, cf[k], beta[k]);
                        errb = fmaf(fabsf(v), sge[q], errb);
                    }
                    else if (d < 44)       hhi[d - 32] = c4[cc];
                    else {                 // tail cos: q = 2*(d-44)+1
                        const int q = 2 * (d - 44) + 1;
                        const float v = c4[cc];
                        const float* cf = scf + q * 9;
#pragma unroll
                        for (int k = 0; k < 9; k++) beta[k] = fmaf(v, cf[k], beta[k]);
                        errb = fmaf(fabsf(v), sge[q], errb);
                    }
                }
            }
        }
        const float margin = fmaf(4.f, errb, 0.2f);

        ull hv[JHEAD], bp[5];
#pragma unroll
        for (int j = 0; j < JHEAD; j++) hv[j] = pack2(hlo[j], hhi[j]);
        bp[0] = pack2(beta[0], beta[1]);
        bp[1] = pack2(beta[2], beta[3]);
        bp[2] = pack2(beta[4], beta[5]);
        bp[3] = pack2(beta[6], beta[7]);
        bp[4] = pack2(beta[8], 0.f);

        // ---- scan 512 codes: top-3 approx values, top-2 codes ----
        float b1 = 3.4e38f, b2 = 3.4e38f, b3 = 3.4e38f;
        int   s1 = 0, s2 = 0;
#pragma unroll 2
        for (int code = 0; code < NCODE; code++) {
            const ull* row = stbl + code * TROW;
            const ulonglong2* rp = (const ulonglong2*)row;
            ulonglong2 l0 = rp[0], l1 = rp[1], l2 = rp[2];
            ulonglong2 l3 = rp[3], l4 = rp[4], l5 = rp[5];
            ulonglong2 l6 = rp[6], l7 = rp[7];
            ull p4 = row[16];
            float cn = __uint_as_float((uint32_t)row[17]);
            ull a = 0ull, b = 0ull;
            ffma2(a, hv[0],  l0.x); ffma2(b, hv[1],  l0.y);
            ffma2(a, hv[2],  l1.x); ffma2(b, hv[3],  l1.y);
            ffma2(a, hv[4],  l2.x); ffma2(b, hv[5],  l2.y);
            ffma2(a, hv[6],  l3.x); ffma2(b, hv[7],  l3.y);
            ffma2(a, hv[8],  l4.x); ffma2(b, hv[9],  l4.y);
            ffma2(a, hv[10], l5.x); ffma2(b, hv[11], l5.y);
            ffma2(a, bp[0],  l6.x); ffma2(b, bp[1],  l6.y);
            ffma2(a, bp[2],  l7.x); ffma2(b, bp[3],  l7.y);
            ffma2(a, bp[4],  p4);
            float alo, ahi, blo, bhi;
            unpack2(a, alo, ahi); unpack2(b, blo, bhi);
            float dot = __fadd_rn(__fadd_rn(alo, ahi), __fadd_rn(blo, bhi));
            float w = fmaf(-2.f, dot, cn);          // w = cn - 2*dot~ ; dist = vn + w
            if (w < b2) {
                b3 = b2;
                if (w < b1) { b2 = b1; s2 = s1; b1 = w; s1 = code; }
                else        { b2 = w;  s2 = code; }
            } else {
                b3 = fminf(b3, w);
            }
        }

        // ---- exact refine: margin-certified candidate set ----
        float bestd; int bests;
        if (b3 >= b1 + margin) {
            // certified: true argmin in {s1, s2}
            float d1, d2;
            {
                const float4* vp = (const float4*)vrow;
                const float4* cp = (const float4*)(scb + s1 * 64);
                float dot = 0.f;
#pragma unroll
                for (int kk = 0; kk < 16; kk++) {
                    float4 av = vp[kk], bv = cp[kk];
                    dot = fmaf(av.x, bv.x, dot);
                    dot = fmaf(av.y, bv.y, dot);
                    dot = fmaf(av.z, bv.z, dot);
                    dot = fmaf(av.w, bv.w, dot);
                }
                d1 = __fadd_rn(fmaf(-2.f, dot, vn), g_cn[s1]);
            }
            {
                const float4* vp = (const float4*)vrow;
                const float4* cp = (const float4*)(scb + s2 * 64);
                float dot = 0.f;
#pragma unroll
                for (int kk = 0; kk < 16; kk++) {
                    float4 av = vp[kk], bv = cp[kk];
                    dot = fmaf(av.x, bv.x, dot);
                    dot = fmaf(av.y, bv.y, dot);
                    dot = fmaf(av.z, bv.z, dot);
                    dot = fmaf(av.w, bv.w, dot);
                }
                d2 = __fadd_rn(fmaf(-2.f, dot, vn), g_cn[s2]);
            }
            // first-min-wins: lexicographic (dist, code)
            if (d2 < d1 || (d2 == d1 && s2 < s1)) { bestd = d2; bests = s2; }
            else                                  { bestd = d1; bests = s1; }
        } else {
            // rare fallback: full exact scan, ascending, strict <
            bestd = 3.4e38f; bests = 0;
            const float4* vp = (const float4*)vrow;
            for (int code = 0; code < NCODE; code++) {
                const float4* cp = (const float4*)(scb + code * 64);
                float dot = 0.f;
#pragma unroll
                for (int kk = 0; kk < 16; kk++) {
                    float4 av = vp[kk], bv = cp[kk];
                    dot = fmaf(av.x, bv.x, dot);
                    dot = fmaf(av.y, bv.y, dot);
                    dot = fmaf(av.z, bv.z, dot);
                    dot = fmaf(av.w, bv.w, dot);
                }
                float dd = __fadd_rn(fmaf(-2.f, dot, vn), g_cn[code]);
                if (dd < bestd) { bestd = dd; bests = code; }
            }
        }

        // ---- outputs ----
        float er = fmaxf(bestd, 0.f);
        out[ZOFF + vglob] = (float)bests;
        out[EOFF + vglob] = er;
        lacc = __fadd_rn(lacc, __fmul_rn(mask[vglob], er));
        {
            const float4* cp = (const float4*)(scb + bests * 64);
            float4* dst = (float4*)(out + (size_t)vglob * 64);
#pragma unroll
            for (int i = 0; i < 16; i++) dst[i] = cp[i];
        }
    }

    // ---- l_commit block partial ----
    sred[t] = lacc;
    __syncthreads();
    for (int o = NTHR / 2; o > 0; o >>= 1) {
        if (t < o) sred[t] = __fadd_rn(sred[t], sred[t + o]);
        __syncthreads();
    }
    if (t == 0) g_part[blockIdx.x] = sred[0];
}

// ---------------------------------------------------------------------------
__global__ void vq_final(float* __restrict__ out) {
    __shared__ float s[256];
    int t = threadIdx.x;
    s[t] = (t < NBLK) ? g_part[t] : 0.f;
    __syncthreads();
    for (int o = 128; o > 0; o >>= 1) {
        if (t < o) s[t] = __fadd_rn(s[t], s[t + o]);
        __syncthreads();
    }
    if (t == 0) out[LOFF] = __fmul_rn(s[0], (1.0f / 131072.0f));
}

// ---------------------------------------------------------------------------
extern "C" void kernel_launch(void* const* d_in, const int* in_sizes, int n_in,
                              void* d_out, int out_size) {
    (void)in_sizes; (void)n_in; (void)out_size;
    const float* vecs = (const float*)d_in[0];
    const float* mask = (const float*)d_in[1];
    float* out = (float*)d_out;

    cudaFuncSetAttribute(vq_main, cudaFuncAttributeMaxDynamicSharedMemorySize, SMEM_BYTES);

    vq_init<<<NCODE, 64>>>();
    vq_init2<<<1, 512>>>();
    vq_main<<<NBLK, NTHR, SMEM_BYTES>>>(vecs, mask, out);
    vq_final<<<1, 256>>>(out);
}

// round 12
// speedup vs baseline: 2.4249x; 2.4249x over previous
#include <cuda_runtime.h>
#include <math.h>
#include <stdint.h>

// ---------------------------------------------------------------------------
// SimpleVQ: B=32, H=1, L=4096, D=64, S=512
// out (f32): quantized[NVEC*64] | z[NVEC] | l_commit | errs2[NVEC]
// Chebyshev-compressed (34 aug dims) FFMA2 scan, bf16 buffer, threshold
// certification (NO fallback path), exact fp32 refine. 256-thread chassis.
// ---------------------------------------------------------------------------

typedef unsigned long long ull;

#define NVEC   131072
#define NCODE  512
#define ZOFF   8388608
#define LOFF   8519680
#define EOFF   8519681
#define NBLK   148
#define NTHR   256
#define NTILES 2048            // NVEC / 64 rows per tile

#define JHEAD  12
#define NSEQ   40
#define DSTRIDE 276            // bytes; 69 words, gcd(69,32)=1 -> conflict-free

// ---- smem layout (bytes) ---------------------------------------------------
#define ST4    0               // aug quad table [256 pairs][17] float4   69632
#define SDISTB 69632           // bf16 w buffer, per-thread 276B          70656
#define SCN    140288          // fp32 cn [512]                            2048
#define SCF    142336          // coef [40][9]                             1440
#define SGE    143776          // E [40]                                    160
#define SMIN   143936          // u32 [64]                                  256
#define SKEY   144192          // ull [64]                                  512
#define SRED   144704          // float [256]                              1024
#define SMEM_BYTES 145728

__device__ float g_cbf[512 * 64];
__device__ float g_cn[512];
__device__ float g_rt[512];
__device__ float g_T4[256 * 17 * 4];   // quad-packed aug table
__device__ float g_cf[NSEQ * 9];
__device__ float g_E[NSEQ];
__device__ float g_part[NBLK];

// ---- helpers ---------------------------------------------------------------
__device__ __forceinline__ ull pack2(float lo, float hi) {
    ull r; asm("mov.b64 %0, {%1, %2};" : "=l"(r) : "f"(lo), "f"(hi)); return r;
}
__device__ __forceinline__ void unpack2(ull v, float &lo, float &hi) {
    asm("mov.b64 {%0, %1}, %2;" : "=f"(lo), "=f"(hi) : "l"(v));
}
__device__ __forceinline__ void ffma2(ull &acc, ull a, ull b) {
    asm("fma.rn.f32x2 %0, %1, %2, %0;" : "+l"(acc) : "l"(a), "l"(b));
}
__device__ __forceinline__ uint32_t bf2(float lo, float hi) {
    uint32_t r; asm("cvt.rn.bf16x2.f32 %0, %1, %2;" : "=r"(r) : "f"(hi), "f"(lo)); return r;
}
__device__ __forceinline__ uint32_t enc32(float f) {
    uint32_t u = __float_as_uint(f);
    return (u & 0x80000000u) ? ~u : (u | 0x80000000u);
}
__device__ __forceinline__ float dec32(uint32_t m) {
    uint32_t u = (m & 0x80000000u) ? (m & 0x7FFFFFFFu) : ~m;
    return __uint_as_float(u);
}

// ---------------------------------------------------------------------------
// Init 1: codebook (double trig; identical to all passing rounds)
// ---------------------------------------------------------------------------
__global__ void vq_init() {
    __shared__ float red[64];
    const int s = blockIdx.x;
    const int d = threadIdx.x;
    const int j = d & 31;

    double expn = -((double)(2 * j) / 64.0);
    float  il   = (float)pow(100000.0, expn);
    float  pre  = __fmul_rn((float)s, il);
    float  e    = (d < 32) ? (float)sin((double)pre) : (float)cos((double)pre);

    red[d] = __fmul_rn(e, e);
    __syncthreads();
    for (int o = 32; o > 0; o >>= 1) {
        if (d < o) red[d] = __fadd_rn(red[d], red[d + o]);
        __syncthreads();
    }
    float m = __fadd_rn(__fmul_rn(red[0], (1.0f / 64.0f)), 1e-6f);
    __syncthreads();
    float r = (float)(1.0 / sqrt((double)m));
    float c = __fmul_rn(__fmul_rn(e, r), 0.35355339059327373f);

    g_cbf[s * 64 + d] = c;
    if (d == 0) g_rt[s] = __fmul_rn(r, 0.35355339059327373f);

    red[d] = __fmul_rn(c, c);
    __syncthreads();
    for (int o = 32; o > 0; o >>= 1) {
        if (d < o) red[d] = __fadd_rn(red[d], red[d + o]);
        __syncthreads();
    }
    if (d == 0) g_cn[s] = red[0];
}

// ---------------------------------------------------------------------------
// Init 2: Chebyshev fits + certified errors (passed 3x) + quad table build.
// ---------------------------------------------------------------------------
__global__ void vq_init2() {
    __shared__ float scf[NSEQ][9];
    __shared__ int   seps[NSEQ];
    __shared__ float red[512];
    const int t = threadIdx.x;

    if (t < NSEQ) {
        const int jj = t >> 1, trig = t & 1;
        const int j  = JHEAD + jj;
        float w = (float)pow(100000.0, -((double)(2 * j) / 64.0));
        float c[9];
#pragma unroll
        for (int k = 0; k < 9; k++) c[k] = 0.f;
        for (int mnode = 0; mnode < 33; mnode++) {
            float th = (float)M_PI * ((float)mnode + 0.5f) / 33.f;
            float ct = cosf(th);
            float x  = 255.5f + 255.5f * ct;
            float f  = trig ? cosf(w * x) : sinf(w * x);
            float tk0 = 1.f, tk1 = ct;
            c[0] += f; c[1] += f * ct;
#pragma unroll
            for (int k = 2; k < 9; k++) {
                float tk = 2.f * ct * tk1 - tk0;
                c[k] += f * tk;
                tk0 = tk1; tk1 = tk;
            }
        }
#pragma unroll
        for (int k = 0; k < 9; k++) c[k] *= (2.f / 33.f);
        c[0] *= 0.5f;
#pragma unroll
        for (int k = 0; k < 9; k++) { scf[t][k] = c[k]; g_cf[t * 9 + k] = c[k]; }
        seps[t] = 0;
    }
    __syncthreads();

    const int s = t;
    const float rt = g_rt[s];
    double y = ((double)s - 255.5) / 255.5;
    double T[9];
    T[0] = 1.0; T[1] = y;
#pragma unroll
    for (int k = 2; k < 9; k++) T[k] = 2.0 * y * T[k - 1] - T[k - 2];

    // quad table: aug dims d: 0..23 head (even=sin j, odd=cos j), 24..32 rt*T_k, 33 pad
    {
        const int p = s >> 1, col = s & 1;
#pragma unroll
        for (int d = 0; d < 34; d++) {
            float val;
            if (d < 24) val = (d & 1) ? g_cbf[s * 64 + 32 + (d >> 1)]
                                      : g_cbf[s * 64 + (d >> 1)];
            else if (d < 33) val = (float)((double)rt * T[d - 24]);
            else val = 0.f;
            g_T4[((p * 17 + (d >> 1)) << 2) + ((d & 1) << 1) + col] = val;
        }
    }

    // certified eps (truth = exact kernel-1 formula)
    for (int q = 0; q < NSEQ; q++) {
        const int jj = q >> 1, trig = q & 1;
        const int j  = JHEAD + jj;
        double expn = -((double)(2 * j) / 64.0);
        float  il   = (float)pow(100000.0, expn);
        float  pre  = __fmul_rn((float)s, il);
        double truth = trig ? cos((double)pre) : sin((double)pre);
        double fit = 0.0;
#pragma unroll
        for (int k = 0; k < 9; k++) fit += (double)scf[q][k] * T[k];
        float err = (float)fabs(truth - fit);
        atomicMax(&seps[q], __float_as_int(err));
    }

    red[t] = rt;
    __syncthreads();
    for (int o = 256; o > 0; o >>= 1) {
        if (t < o) red[t] = fmaxf(red[t], red[t + o]);
        __syncthreads();
    }
    if (t < NSEQ) g_E[t] = __int_as_float(seps[t]) * red[0];
}

// ---------------------------------------------------------------------------
__device__ __forceinline__ void refine(const float* __restrict__ vrow,
                                       int row, int code,
                                       float vn, const float* scn, ull* skey) {
    const float4* vp = (const float4*)vrow;
    const float4* cp = (const float4*)(g_cbf + (size_t)code * 64);
    float d0 = 0.f, d1 = 0.f, d2 = 0.f, d3 = 0.f;
#pragma unroll
    for (int kk = 0; kk < 4; kk++) {
        float4 a0 = vp[4*kk],   b0 = __ldg(cp + 4*kk);
        float4 a1 = vp[4*kk+1], b1 = __ldg(cp + 4*kk+1);
        float4 a2 = vp[4*kk+2], b2 = __ldg(cp + 4*kk+2);
        float4 a3 = vp[4*kk+3], b3 = __ldg(cp + 4*kk+3);
        d0 = fmaf(a0.x, b0.x, d0); d0 = fmaf(a0.y, b0.y, d0);
        d0 = fmaf(a0.z, b0.z, d0); d0 = fmaf(a0.w, b0.w, d0);
        d1 = fmaf(a1.x, b1.x, d1); d1 = fmaf(a1.y, b1.y, d1);
        d1 = fmaf(a1.z, b1.z, d1); d1 = fmaf(a1.w, b1.w, d1);
        d2 = fmaf(a2.x, b2.x, d2); d2 = fmaf(a2.y, b2.y, d2);
        d2 = fmaf(a2.z, b2.z, d2); d2 = fmaf(a2.w, b2.w, d2);
        d3 = fmaf(a3.x, b3.x, d3); d3 = fmaf(a3.y, b3.y, d3);
        d3 = fmaf(a3.z, b3.z, d3); d3 = fmaf(a3.w, b3.w, d3);
    }
    float dot = __fadd_rn(__fadd_rn(d0, d1), __fadd_rn(d2, d3));
    float dist = __fadd_rn(fmaf(-2.f, dot, vn), scn[code]);
    ull key = ((ull)enc32(dist) << 9) | (uint32_t)code;
    atomicMin(&skey[row], key);
}

// ---------------------------------------------------------------------------
__global__ void __launch_bounds__(NTHR) vq_main(const float* __restrict__ vecs,
                                                const float* __restrict__ mask,
                                                float* __restrict__ out) {
    extern __shared__ unsigned char smem[];
    ulonglong2* st4  = (ulonglong2*)(smem + ST4);
    float*      scn  = (float*)(smem + SCN);
    float*      scf  = (float*)(smem + SCF);
    float*      sge  = (float*)(smem + SGE);
    uint32_t*   smin = (uint32_t*)(smem + SMIN);
    ull*        skey = (ull*)(smem + SKEY);
    float*      sred = (float*)(smem + SRED);

    const int t   = threadIdx.x;
    const int row = t >> 2;          // 0..63
    const int seg = t & 3;

    // ---- stage tables ----
    {
        uint4* d4 = (uint4*)st4;
        const uint4* s4 = (const uint4*)g_T4;
        for (int i = t; i < 256 * 17; i += NTHR) d4[i] = s4[i];
        for (int i = t; i < NCODE; i += NTHR) scn[i] = g_cn[i];
        for (int i = t; i < NSEQ * 9; i += NTHR) scf[i] = g_cf[i];
        if (t < NSEQ) sge[t] = g_E[t];
    }
    __syncthreads();

    float lacc = 0.f;

    for (int tile = blockIdx.x; tile < NTILES; tile += NBLK) {
        const int vglob = tile * 64 + row;
        const float* vrow = vecs + (size_t)vglob * 64;

        // ---- build augmented vector: vn exact ascending, head + beta ----
        float ua[34];
        ua[33] = 0.f;
        float beta[9];
#pragma unroll
        for (int k = 0; k < 9; k++) beta[k] = 0.f;
        float errb = 0.f;
        float vn = 0.f;
        {
            const float4* vp = (const float4*)vrow;
#pragma unroll
            for (int i = 0; i < 16; i++) {
                float4 x = vp[i];
                vn = __fadd_rn(vn, __fmul_rn(x.x, x.x));
                vn = __fadd_rn(vn, __fmul_rn(x.y, x.y));
                vn = __fadd_rn(vn, __fmul_rn(x.z, x.z));
                vn = __fadd_rn(vn, __fmul_rn(x.w, x.w));
                float c4[4] = {x.x, x.y, x.z, x.w};
#pragma unroll
                for (int cc = 0; cc < 4; cc++) {
                    const int d = 4 * i + cc;
                    if (d < 12)       ua[2 * d] = c4[cc];
                    else if (d < 32) {
                        const int q = 2 * (d - 12);
                        const float v = c4[cc];
                        const float* cf = scf + q * 9;
#pragma unroll
                        for (int k = 0; k < 9; k++) beta[k] = fmaf(v, cf[k], beta[k]);
                        errb = fmaf(fabsf(v), sge[q], errb);
                    }
                    else if (d < 44)  ua[2 * (d - 32) + 1] = c4[cc];
                    else {
                        const int q = 2 * (d - 44) + 1;
                        const float v = c4[cc];
                        const float* cf = scf + q * 9;
#pragma unroll
                        for (int k = 0; k < 9; k++) beta[k] = fmaf(v, cf[k], beta[k]);
                        errb = fmaf(fabsf(v), sge[q], errb);
                    }
                }
            }
        }
#pragma unroll
        for (int k = 0; k < 9; k++) ua[24 + k] = beta[k];
        const float margin = fmaf(4.f, errb, 0.30f);

        // pre-pack broadcast pairs (both lanes = same value)
        ull ubc[34];
#pragma unroll
        for (int d = 0; d < 34; d++) ubc[d] = pack2(ua[d], ua[d]);

        if (t < 64) { smin[t] = 0xFFFFFFFFu; skey[t] = ~0ull; }
        __syncthreads();

        // ---- scan: 64 code-pairs, p = seg + 4m ----
        float localmin = 3.4e38f;
        uint32_t* dbuf = (uint32_t*)(smem + SDISTB + t * DSTRIDE);
#pragma unroll 2
        for (int m = 0; m < 64; m++) {
            const int p = seg + 4 * m;
            const ulonglong2* rp = st4 + p * 17;
            ull a0 = 0ull, a1 = 0ull;
#pragma unroll
            for (int j2 = 0; j2 < 17; j2++) {
                ulonglong2 q = rp[j2];
                ffma2(a0, ubc[2 * j2], q.x);
                ffma2(a1, ubc[2 * j2 + 1], q.y);
            }
            float e0, e1, o0, o1;
            unpack2(a0, e0, e1); unpack2(a1, o0, o1);
            const int c0 = 2 * p;
            float w0 = fmaf(-2.f, __fadd_rn(e0, o0), scn[c0]);
            float w1 = fmaf(-2.f, __fadd_rn(e1, o1), scn[c0 + 1]);
            localmin = fminf(localmin, fminf(w0, w1));
            dbuf[m] = bf2(w0, w1);
        }
        atomicMin(&smin[row], enc32(localmin));
        __syncthreads();

        // ---- threshold pass + exact refine (no fallback needed) ----
        {
            const float thr = dec32(smin[row]) + margin;
#pragma unroll 1
            for (int m = 0; m < 64; m++) {
                uint32_t wv = dbuf[m];
                float flo = __uint_as_float(wv << 16);
                float fhi = __uint_as_float(wv & 0xFFFF0000u);
                if (flo < thr) refine(vrow, row, 2 * (seg + 4 * m),     vn, scn, skey);
                if (fhi < thr) refine(vrow, row, 2 * (seg + 4 * m) + 1, vn, scn, skey);
            }
        }
        __syncthreads();

        // ---- outputs ----
        ull key = skey[row];
        int bests = (int)(key & 511);
        if (seg == 0) {
            float dist = dec32((uint32_t)(key >> 9));
            float er = fmaxf(dist, 0.f);
            out[ZOFF + vglob] = (float)bests;
            out[EOFF + vglob] = er;
            lacc = __fadd_rn(lacc, __fmul_rn(mask[vglob], er));
        }
        {
            const float4* cp = (const float4*)(g_cbf + (size_t)bests * 64 + seg * 16);
            float4* dst = (float4*)(out + (size_t)vglob * 64 + seg * 16);
            dst[0] = __ldg(cp); dst[1] = __ldg(cp + 1);
            dst[2] = __ldg(cp + 2); dst[3] = __ldg(cp + 3);
        }
        __syncthreads();
    }

    // ---- l_commit block partial ----
    sred[t] = lacc;
    __syncthreads();
    for (int o = NTHR / 2; o > 0; o >>= 1) {
        if (t < o) sred[t] = __fadd_rn(sred[t], sred[t + o]);
        __syncthreads();
    }
    if (t == 0) g_part[blockIdx.x] = sred[0];
}

// ---------------------------------------------------------------------------
__global__ void vq_final(float* __restrict__ out) {
    __shared__ float s[256];
    int t = threadIdx.x;
    s[t] = (t < NBLK) ? g_part[t] : 0.f;
    __syncthreads();
    for (int o = 128; o > 0; o >>= 1) {
        if (t < o) s[t] = __fadd_rn(s[t], s[t + o]);
        __syncthreads();
    }
    if (t == 0) out[LOFF] = __fmul_rn(s[0], (1.0f / 131072.0f));
}

// ---------------------------------------------------------------------------
extern "C" void kernel_launch(void* const* d_in, const int* in_sizes, int n_in,
                              void* d_out, int out_size) {
    (void)in_sizes; (void)n_in; (void)out_size;
    const float* vecs = (const float*)d_in[0];
    const float* mask = (const float*)d_in[1];
    float* out = (float*)d_out;

    cudaFuncSetAttribute(vq_main, cudaFuncAttributeMaxDynamicSharedMemorySize, SMEM_BYTES);

    vq_init<<<NCODE, 64>>>();
    vq_init2<<<1, 512>>>();
    vq_main<<<NBLK, NTHR, SMEM_BYTES>>>(vecs, mask, out);
    vq_final<<<1, 256>>>(out);
}

// round 13
// speedup vs baseline: 5.3195x; 2.1937x over previous
#include <cuda_runtime.h>
#include <math.h>

// ---------------------------------------------------------------------------
// SimpleVQ: B=32, H=1, L=4096, D=64, S=512
// Outputs (concatenated f32): quantized[B*H*L*D] | z[B*H*L] | l_commit | errs2[B*H*L]
// R1 main kernel (measured 232us, roofline-optimal fp32) + parallel init (6us).
// ---------------------------------------------------------------------------

typedef unsigned long long ull;

#define NVEC   131072            // B*H*L
#define DIMD   64
#define NCODE  512
#define NPAIR  256               // NCODE/2
#define ZOFF   8388608           // NVEC*DIMD
#define LOFF   8519680           // ZOFF + NVEC
#define EOFF   8519681           // LOFF + 1
#define NBLK   256               // main-kernel grid
#define SMEM_BYTES (131072 + 2048 + 1024)   // codebook(128KB) + cnorm(2KB) + reduce(1KB)

// Codebook in pair-quad layout: g_cbq[p*32+j] = { c[2p][2j], c[2p+1][2j], c[2p][2j+1], c[2p+1][2j+1] }
__device__ float4 g_cbq[NPAIR * 32];
__device__ float  g_cn[NCODE];        // ||c_s||^2
__device__ float  g_part[NBLK];       // per-block partial sums for l_commit

// ---- packed f32x2 helpers (Blackwell) -------------------------------------
__device__ __forceinline__ ull pack2(float x, float y) {
    ull r; asm("mov.b64 %0, {%1, %2};" : "=l"(r) : "f"(x), "f"(y)); return r;
}
__device__ __forceinline__ void unpack2(ull v, float &x, float &y) {
    asm("mov.b64 {%0, %1}, %2;" : "=f"(x), "=f"(y) : "l"(v));
}
__device__ __forceinline__ void ffma2(ull &acc, ull a, ull b) {
    // acc = a*b + acc, per-lane fp32 fma (packed 2x)
    asm("fma.rn.f32x2 %0, %1, %2, %0;" : "+l"(acc) : "l"(a), "l"(b));
}

// ---------------------------------------------------------------------------
// Init: 512 blocks (one per codeword) x 64 threads (one per dim).
// Double trig (exact vs reference's fp32 libdevice); writes R1's pair-quad
// layout. This init structure passed in R2/R5/R7/R8 at ~6us.
// ---------------------------------------------------------------------------
__global__ void vq_init() {
    __shared__ float red[64];
    const int s = blockIdx.x;
    const int d = threadIdx.x;
    const int j = d & 31;

    double expn = -((double)(2 * j) / 64.0);
    float  il   = (float)pow(100000.0, expn);
    float  pre  = __fmul_rn((float)s, il);
    float  e    = (d < 32) ? (float)sin((double)pre) : (float)cos((double)pre);

    // reduce sum of squares over 64 threads (fixed-shape tree)
    red[d] = __fmul_rn(e, e);
    __syncthreads();
    for (int o = 32; o > 0; o >>= 1) {
        if (d < o) red[d] = __fadd_rn(red[d], red[d + o]);
        __syncthreads();
    }
    float m = __fadd_rn(__fmul_rn(red[0], (1.0f / 64.0f)), 1e-6f);
    __syncthreads();
    float r = (float)(1.0 / sqrt((double)m));

    float c = __fmul_rn(__fmul_rn(e, r), 0.35355339059327373f);  // * 64^-0.25

    // store into R1 pair-quad layout
    float* cb = (float*)g_cbq;
    const int p = s >> 1, col = s & 1;
    cb[(p * 32 + (d >> 1)) * 4 + (d & 1) * 2 + col] = c;

    // ||c||^2 via same tree
    red[d] = __fmul_rn(c, c);
    __syncthreads();
    for (int o = 32; o > 0; o >>= 1) {
        if (d < o) red[d] = __fadd_rn(red[d], red[d + o]);
        __syncthreads();
    }
    if (d == 0) g_cn[s] = red[0];
}

// ---------------------------------------------------------------------------
// Main: each block (256 thr) owns 512 vectors (2/thread), codebook in smem.
// Inner loop: 2 codeword-pairs x 2 vectors via packed FFMA2, sequential-K
// accumulation, first-min-wins argmin. (Verbatim R1: measured 232us.)
// ---------------------------------------------------------------------------
__global__ void __launch_bounds__(256) vq_main(const float* __restrict__ vecs,
                                               const float* __restrict__ mask,
                                               float* __restrict__ out) {
    extern __shared__ unsigned char smem[];
    float4*     scbf = (float4*)smem;
    ulonglong2* scb  = (ulonglong2*)smem;
    float*      scn  = (float*)(smem + 131072);
    float*      sred = scn + NCODE;

    for (int i = threadIdx.x; i < NPAIR * 32; i += 256) scbf[i] = g_cbq[i];
    for (int i = threadIdx.x; i < NCODE; i += 256) scn[i] = g_cn[i];
    __syncthreads();

    const int t  = threadIdx.x;
    const int v0 = blockIdx.x * 512 + t;
    const int v1 = v0 + 256;

    float va[64], vb[64];
    {
        const float4* pa = (const float4*)(vecs + (size_t)v0 * DIMD);
        const float4* pb = (const float4*)(vecs + (size_t)v1 * DIMD);
#pragma unroll
        for (int i = 0; i < 16; i++) {
            float4 x = pa[i];
            va[4*i] = x.x; va[4*i+1] = x.y; va[4*i+2] = x.z; va[4*i+3] = x.w;
            float4 y = pb[i];
            vb[4*i] = y.x; vb[4*i+1] = y.y; vb[4*i+2] = y.z; vb[4*i+3] = y.w;
        }
    }
    // ||v||^2 : square-then-sum (no fma contraction), ascending order
    float vn0 = 0.f, vn1 = 0.f;
#pragma unroll
    for (int d = 0; d < 64; d++) {
        vn0 = __fadd_rn(vn0, __fmul_rn(va[d], va[d]));
        vn1 = __fadd_rn(vn1, __fmul_rn(vb[d], vb[d]));
    }

    float best0 = 3.4e38f, best1 = 3.4e38f;
    int   bi0 = 0, bi1 = 0;

#pragma unroll 1
    for (int p = 0; p < NPAIR; p += 2) {
        ull a00 = 0ull, a01 = 0ull, a10 = 0ull, a11 = 0ull;  // (0.f,0.f)
#pragma unroll
        for (int j = 0; j < 32; j++) {
            ulonglong2 c0 = scb[(p + 0) * 32 + j];
            ulonglong2 c1 = scb[(p + 1) * 32 + j];
            ull w0 = pack2(va[2*j],     va[2*j]);
            ull w1 = pack2(va[2*j + 1], va[2*j + 1]);
            ull u0 = pack2(vb[2*j],     vb[2*j]);
            ull u1 = pack2(vb[2*j + 1], vb[2*j + 1]);
            ffma2(a00, w0, c0.x); ffma2(a00, w1, c0.y);
            ffma2(a01, w0, c1.x); ffma2(a01, w1, c1.y);
            ffma2(a10, u0, c0.x); ffma2(a10, u1, c0.y);
            ffma2(a11, u0, c1.x); ffma2(a11, u1, c1.y);
        }
        float q0, q1, q2, q3, r0, r1, r2, r3;
        unpack2(a00, q0, q1); unpack2(a01, q2, q3);
        unpack2(a10, r0, r1); unpack2(a11, r2, r3);
        const int s0 = 2 * p;
        const float cna = scn[s0], cnb = scn[s0 + 1], cnc = scn[s0 + 2], cnd = scn[s0 + 3];
        // dist = (||v||^2 - 2*dot) + ||c||^2   (reference rounding structure)
        float d0 = __fadd_rn(fmaf(-2.f, q0, vn0), cna);
        float d1 = __fadd_rn(fmaf(-2.f, q1, vn0), cnb);
        float d2 = __fadd_rn(fmaf(-2.f, q2, vn0), cnc);
        float d3 = __fadd_rn(fmaf(-2.f, q3, vn0), cnd);
        if (d0 < best0) { best0 = d0; bi0 = s0;     }
        if (d1 < best0) { best0 = d1; bi0 = s0 + 1; }
        if (d2 < best0) { best0 = d2; bi0 = s0 + 2; }
        if (d3 < best0) { best0 = d3; bi0 = s0 + 3; }
        float e0 = __fadd_rn(fmaf(-2.f, r0, vn1), cna);
        float e1 = __fadd_rn(fmaf(-2.f, r1, vn1), cnb);
        float e2 = __fadd_rn(fmaf(-2.f, r2, vn1), cnc);
        float e3 = __fadd_rn(fmaf(-2.f, r3, vn1), cnd);
        if (e0 < best1) { best1 = e0; bi1 = s0;     }
        if (e1 < best1) { best1 = e1; bi1 = s0 + 1; }
        if (e2 < best1) { best1 = e2; bi1 = s0 + 2; }
        if (e3 < best1) { best1 = e3; bi1 = s0 + 3; }
    }

    // quantized = codebook[z]  (STE terms cancel exactly)
    {
        int pw = bi0 >> 1, col = bi0 & 1;
        float2* dst = (float2*)(out + (size_t)v0 * DIMD);
#pragma unroll
        for (int j = 0; j < 32; j++) {
            float4 q = scbf[pw * 32 + j];
            float2 w; w.x = col ? q.y : q.x; w.y = col ? q.w : q.z;
            dst[j] = w;
        }
    }
    {
        int pw = bi1 >> 1, col = bi1 & 1;
        float2* dst = (float2*)(out + (size_t)v1 * DIMD);
#pragma unroll
        for (int j = 0; j < 32; j++) {
            float4 q = scbf[pw * 32 + j];
            float2 w; w.x = col ? q.y : q.x; w.y = col ? q.w : q.z;
            dst[j] = w;
        }
    }

    out[ZOFF + v0] = (float)bi0;
    out[ZOFF + v1] = (float)bi1;
    float er0 = fmaxf(best0, 0.f);
    float er1 = fmaxf(best1, 0.f);
    out[EOFF + v0] = er0;
    out[EOFF + v1] = er1;

    // deterministic block partial for l_commit
    float lsum = __fadd_rn(__fmul_rn(mask[v0], er0), __fmul_rn(mask[v1], er1));
    sred[t] = lsum;
    __syncthreads();
    for (int o = 128; o > 0; o >>= 1) {
        if (t < o) sred[t] = __fadd_rn(sred[t], sred[t + o]);
        __syncthreads();
    }
    if (t == 0) g_part[blockIdx.x] = sred[0];
}

// ---------------------------------------------------------------------------
// Final: deterministic fixed-order reduction of 256 partials -> l_commit
// ---------------------------------------------------------------------------
__global__ void vq_final(float* __restrict__ out) {
    __shared__ float s[NBLK];
    int t = threadIdx.x;
    s[t] = g_part[t];
    __syncthreads();
    for (int o = NBLK / 2; o > 0; o >>= 1) {
        if (t < o) s[t] = __fadd_rn(s[t], s[t + o]);
        __syncthreads();
    }
    if (t == 0) out[LOFF] = __fmul_rn(s[0], (1.0f / 131072.0f));
}

// ---------------------------------------------------------------------------
extern "C" void kernel_launch(void* const* d_in, const int* in_sizes, int n_in,
                              void* d_out, int out_size) {
    (void)in_sizes; (void)n_in; (void)out_size;
    const float* vecs = (const float*)d_in[0];   // [32,1,4096,64] f32
    const float* mask = (const float*)d_in[1];   // [32,4096] f32
    float* out = (float*)d_out;

    cudaFuncSetAttribute(vq_main, cudaFuncAttributeMaxDynamicSharedMemorySize, SMEM_BYTES);

    vq_init<<<NCODE, 64>>>();
    vq_main<<<NBLK, 256, SMEM_BYTES>>>(vecs, mask, out);
    vq_final<<<1, NBLK>>>(out);
}